// round 10
// baseline (speedup 1.0000x reference)
#include <cuda_runtime.h>
#include <cstddef>
#include <cstdint>

#define B_   2
#define N_   768
#define BN_  1536
#define D_   512
#define E_   64
#define LN_EPS 1e-5f
#define PADR 68            // kC smem row pitch (floats)
#define XP   130           // kB x-tile pitch (floats)
#define WP   66            // kB weight-tile pitch (floats)
#define JT   8             // kC j-tiles per block

typedef unsigned long long ull;

// ---------------- scratch ----------------
__device__ float g_Rc[BN_ * E_];    // centered R'
__device__ float g_Cc[BN_ * E_];    // centered C'
__device__ float g_varR[BN_];
__device__ float g_varC[BN_];

// -------- f32x2 helpers --------
__device__ __forceinline__ void ffma2(ull& d, ull a, ull b) {
    asm("fma.rn.f32x2 %0, %1, %2, %0;" : "+l"(d) : "l"(a), "l"(b));
}
__device__ __forceinline__ ull pack2(float x) {
    ull r; unsigned u = __float_as_uint(x);
    asm("mov.b64 %0, {%1, %1};" : "=l"(r) : "r"(u));
    return r;
}

// ---------------- kernel B: the entire prologue, fused (unchanged R9) --------
extern __shared__ float sm_b[];
__global__ void __launch_bounds__(256) kB(const float* __restrict__ x,
                                          const float* __restrict__ Wr,
                                          const float* __restrict__ Wc,
                                          const float* __restrict__ We) {
    float* xs  = sm_b;                 // 2080
    float* wrs = sm_b + 2080;          // 8448
    float* wcs = wrs + 8448;           // 8448
    float* wes = wcs + 8448;           // 4160 (pitch 65)
    float* Trw = wes + 4160;           // 2048
    float* Tcw = Trw + 2048;           // 2048
    float* P   = sm_b + 2080;          // alias 16384 <= 16896

    int tid  = threadIdx.x;
    int f2   = tid & 31;
    int w    = tid >> 5;
    int row0 = blockIdx.x * 16;

    for (int idx = tid; idx < 4096; idx += 256) {
        int f = idx >> 6, e = idx & 63;
        wes[e * 65 + f] = We[f * E_ + e];
    }

    ull aR[16], aC[16];
#pragma unroll
    for (int r = 0; r < 16; r++) { aR[r] = 0ULL; aC[r] = 0ULL; }

    for (int c = 0; c < 4; c++) {
        int d0 = c * 128;
        for (int idx = tid; idx < 4096; idx += 256) {
            int fp = idx >> 7;
            int dd = idx & 127;
            float2 vr, vc;
            vr.x = Wr[(size_t)(2 * fp) * D_ + d0 + dd];
            vr.y = Wr[(size_t)(2 * fp + 1) * D_ + d0 + dd];
            vc.x = Wc[(size_t)(2 * fp) * D_ + d0 + dd];
            vc.y = Wc[(size_t)(2 * fp + 1) * D_ + d0 + dd];
            *(float2*)(wrs + dd * WP + 2 * fp) = vr;
            *(float2*)(wcs + dd * WP + 2 * fp) = vc;
        }
        for (int idx = tid; idx < 1024; idx += 256) {
            int r = idx >> 6, dd2 = idx & 63;
            *(float2*)(xs + r * XP + dd2 * 2) =
                *(const float2*)(x + (size_t)(row0 + r) * D_ + d0 + dd2 * 2);
        }
        __syncthreads();

        int wbase = w * 16;
#pragma unroll
        for (int p = 0; p < 8; p++) {
            int dd = wbase + p * 2;
            ull wr0 = *(const ull*)(wrs + dd * WP + 2 * f2);
            ull wr1 = *(const ull*)(wrs + (dd + 1) * WP + 2 * f2);
            ull wc0 = *(const ull*)(wcs + dd * WP + 2 * f2);
            ull wc1 = *(const ull*)(wcs + (dd + 1) * WP + 2 * f2);
#pragma unroll
            for (int r = 0; r < 16; r++) {
                float2 xv = *(const float2*)(xs + r * XP + dd);
                ull x0 = pack2(xv.x);
                ull x1 = pack2(xv.y);
                ffma2(aR[r], x0, wr0);
                ffma2(aR[r], x1, wr1);
                ffma2(aC[r], x0, wc0);
                ffma2(aC[r], x1, wc1);
            }
        }
        __syncthreads();
    }

#pragma unroll
    for (int r = 0; r < 16; r++) {
        *(ull*)(P + ((w * 2 + 0) * 16 + r) * E_ + 2 * f2) = aR[r];
        *(ull*)(P + ((w * 2 + 1) * 16 + r) * E_ + 2 * f2) = aC[r];
    }
    __syncthreads();

    {
        int row = tid >> 4;
        int fq  = tid & 15;
        float4 R4 = make_float4(0.f, 0.f, 0.f, 0.f);
        float4 C4 = make_float4(0.f, 0.f, 0.f, 0.f);
#pragma unroll
        for (int ww = 0; ww < 8; ww++) {
            float4 pr = *(const float4*)(P + ((ww * 2 + 0) * 16 + row) * E_ + fq * 4);
            float4 pc = *(const float4*)(P + ((ww * 2 + 1) * 16 + row) * E_ + fq * 4);
            R4.x += pr.x; R4.y += pr.y; R4.z += pr.z; R4.w += pr.w;
            C4.x += pc.x; C4.y += pc.y; C4.z += pc.z; C4.w += pc.w;
        }
        *(float4*)(Trw + row * E_ + fq * 4) = R4;
        *(float4*)(Tcw + row * E_ + fq * 4) = C4;
    }
    __syncthreads();

    int l  = tid & 31;
    int r0 = 2 * w, r1 = 2 * w + 1;
    float aR0l = 0.f, aR0h = 0.f, aR1l = 0.f, aR1h = 0.f;
    float aC0l = 0.f, aC0h = 0.f, aC1l = 0.f, aC1h = 0.f;
#pragma unroll 4
    for (int e = 0; e < E_; e++) {
        float wl = wes[e * 65 + l];
        float wh = wes[e * 65 + l + 32];
        float t0 = Trw[r0 * E_ + e];
        float t1 = Trw[r1 * E_ + e];
        float c0 = Tcw[r0 * E_ + e];
        float c1 = Tcw[r1 * E_ + e];
        aR0l = fmaf(t0, wl, aR0l); aR0h = fmaf(t0, wh, aR0h);
        aR1l = fmaf(t1, wl, aR1l); aR1h = fmaf(t1, wh, aR1h);
        aC0l = fmaf(c0, wl, aC0l); aC0h = fmaf(c0, wh, aC0h);
        aC1l = fmaf(c1, wl, aC1l); aC1h = fmaf(c1, wh, aC1h);
    }

    float sR0 = aR0l + aR0h, qR0 = aR0l * aR0l + aR0h * aR0h;
    float sR1 = aR1l + aR1h, qR1 = aR1l * aR1l + aR1h * aR1h;
    float sC0 = aC0l + aC0h, qC0 = aC0l * aC0l + aC0h * aC0h;
    float sC1 = aC1l + aC1h, qC1 = aC1l * aC1l + aC1h * aC1h;
#pragma unroll
    for (int o = 16; o; o >>= 1) {
        sR0 += __shfl_xor_sync(0xffffffffu, sR0, o);
        qR0 += __shfl_xor_sync(0xffffffffu, qR0, o);
        sR1 += __shfl_xor_sync(0xffffffffu, sR1, o);
        qR1 += __shfl_xor_sync(0xffffffffu, qR1, o);
        sC0 += __shfl_xor_sync(0xffffffffu, sC0, o);
        qC0 += __shfl_xor_sync(0xffffffffu, qC0, o);
        sC1 += __shfl_xor_sync(0xffffffffu, sC1, o);
        qC1 += __shfl_xor_sync(0xffffffffu, qC1, o);
    }
    float mR0 = sR0 * (1.f / 64.f), mR1 = sR1 * (1.f / 64.f);
    float mC0 = sC0 * (1.f / 64.f), mC1 = sC1 * (1.f / 64.f);
    int g0 = row0 + r0, g1 = row0 + r1;
    g_Rc[g0 * E_ + l]      = aR0l - mR0;
    g_Rc[g0 * E_ + l + 32] = aR0h - mR0;
    g_Rc[g1 * E_ + l]      = aR1l - mR1;
    g_Rc[g1 * E_ + l + 32] = aR1h - mR1;
    g_Cc[g0 * E_ + l]      = aC0l - mC0;
    g_Cc[g0 * E_ + l + 32] = aC0h - mC0;
    g_Cc[g1 * E_ + l]      = aC1l - mC1;
    g_Cc[g1 * E_ + l + 32] = aC1h - mC1;
    if (l == 0) {
        g_varR[g0] = qR0 * (1.f / 64.f) - mR0 * mR0;
        g_varR[g1] = qR1 * (1.f / 64.f) - mR1 * mR1;
        g_varC[g0] = qC0 * (1.f / 64.f) - mC0 * mC0;
        g_varC[g1] = qC1 * (1.f / 64.f) - mC1 * mC1;
    }
}

// ---------------- kernel C: register-dot + shfl-reduce epilogue --------------
// grid (48, 2, 6), block 256. Per tile: 32 LDS.128 (2x-broadcast), 1 barrier,
// no rs/inv smem, iv distributed by warp shuffle.
__global__ void __launch_bounds__(256, 4) kC(const float* __restrict__ gamma,
                                             const float* __restrict__ beta,
                                             float* __restrict__ out) {
    __shared__ float cs[2][16 * PADR];
    __shared__ float vC[2][16];

    int i0 = blockIdx.x * 16;
    int b  = blockIdx.y;
    int jg = blockIdx.z;
    int tid = threadIdx.x;
    int rw = tid >> 4;
    int f4 = tid & 15;
    int rowR = b * N_ + i0;
    int jjA  = (f4 >> 1) & 7;      // jj this lane ends up owning (per 8-group)
    int lbase = tid & 16;          // warp-lane base of my 16-lane group

    // R'-row chunk and varR live in registers for the whole kernel
    float4 rr = __ldg((const float4*)(g_Rc + (size_t)(rowR + rw) * E_) + f4);
    float  vr = __ldg(g_varR + rowR + rw);

    // preload j-tile 0
    {
        int rowC = b * N_ + jg * JT * 16;
        ((float4*)(cs[0] + rw * PADR))[f4] =
            __ldg((const float4*)(g_Cc + (size_t)(rowC + rw) * E_) + f4);
        if (tid < 16) vC[0][tid] = g_varC[rowC + tid];
    }

    float4 gm = __ldg((const float4*)gamma + f4);
    float4 bt = __ldg((const float4*)beta + f4);
    float4 u;                       // u = r' * gamma
    u.x = rr.x * gm.x; u.y = rr.y * gm.y; u.z = rr.z * gm.z; u.w = rr.w * gm.w;
    __syncthreads();

    for (int t = 0; t < JT; t++) {
        int cur = t & 1, nxt = cur ^ 1;
        const float* csc = cs[cur];

        // register prefetch of next tile (hidden behind dots + stores)
        float4 pc = make_float4(0.f, 0.f, 0.f, 0.f);
        float  pv = 0.f;
        if (t + 1 < JT) {
            int rowCn = b * N_ + (jg * JT + t + 1) * 16;
            pc = __ldg((const float4*)(g_Cc + (size_t)(rowCn + rw) * E_) + f4);
            if (tid < 16) pv = g_varC[rowCn + tid];
        }

        float iv0, iv1;
        float p[8];
        // ---- pass A1: partial dots for jj 0..7 ----
#pragma unroll
        for (int k = 0; k < 8; k++) {
            float4 c = ((const float4*)(csc + k * PADR))[f4];
            p[k] = fmaf(rr.x, c.x, fmaf(rr.y, c.y, fmaf(rr.z, c.z, rr.w * c.w)));
        }
        {   // recursive-halving reduce over the 16 f4 lanes
            bool h8 = (f4 & 8) != 0;
#pragma unroll
            for (int k = 0; k < 4; k++) {
                float mine = h8 ? p[k] : p[k + 4];
                float got = __shfl_xor_sync(0xffffffffu, mine, 8);
                p[k] = (h8 ? p[k + 4] : p[k]) + got;
            }
            bool h4 = (f4 & 4) != 0;
#pragma unroll
            for (int k = 0; k < 2; k++) {
                float mine = h4 ? p[k] : p[k + 2];
                float got = __shfl_xor_sync(0xffffffffu, mine, 4);
                p[k] = (h4 ? p[k + 2] : p[k]) + got;
            }
            bool h2 = (f4 & 2) != 0;
            float mine = h2 ? p[0] : p[1];
            float got = __shfl_xor_sync(0xffffffffu, mine, 2);
            p[0] = (h2 ? p[1] : p[0]) + got;
            p[0] += __shfl_xor_sync(0xffffffffu, p[0], 1);
            iv0 = rsqrtf(vr + vC[cur][jjA] + p[0] * (2.f / 64.f) + LN_EPS);
        }
        // ---- pass A2: jj 8..15 ----
#pragma unroll
        for (int k = 0; k < 8; k++) {
            float4 c = ((const float4*)(csc + (8 + k) * PADR))[f4];
            p[k] = fmaf(rr.x, c.x, fmaf(rr.y, c.y, fmaf(rr.z, c.z, rr.w * c.w)));
        }
        {
            bool h8 = (f4 & 8) != 0;
#pragma unroll
            for (int k = 0; k < 4; k++) {
                float mine = h8 ? p[k] : p[k + 4];
                float got = __shfl_xor_sync(0xffffffffu, mine, 8);
                p[k] = (h8 ? p[k + 4] : p[k]) + got;
            }
            bool h4 = (f4 & 4) != 0;
#pragma unroll
            for (int k = 0; k < 2; k++) {
                float mine = h4 ? p[k] : p[k + 2];
                float got = __shfl_xor_sync(0xffffffffu, mine, 4);
                p[k] = (h4 ? p[k + 2] : p[k]) + got;
            }
            bool h2 = (f4 & 2) != 0;
            float mine = h2 ? p[0] : p[1];
            float got = __shfl_xor_sync(0xffffffffu, mine, 2);
            p[0] = (h2 ? p[1] : p[0]) + got;
            p[0] += __shfl_xor_sync(0xffffffffu, p[0], 1);
            iv1 = rsqrtf(vr + vC[cur][8 + jjA] + p[0] * (2.f / 64.f) + LN_EPS);
        }

        // ---- phase B: streaming stores, iv via warp shuffle (no barrier!) ----
        float4* op = (float4*)out +
                     ((size_t)(b * N_ + i0 + rw) * N_ + (jg * JT + t) * 16) * 16 + f4;
#pragma unroll
        for (int jj = 0; jj < 16; jj++) {
            float4 c = ((const float4*)(csc + jj * PADR))[f4];
            float iv = __shfl_sync(0xffffffffu, (jj < 8) ? iv0 : iv1,
                                   lbase + 2 * (jj & 7));
            float4 o;
            o.x = fmaf(fmaf(c.x, gm.x, u.x), iv, bt.x);
            o.y = fmaf(fmaf(c.y, gm.y, u.y), iv, bt.y);
            o.z = fmaf(fmaf(c.z, gm.z, u.z), iv, bt.z);
            o.w = fmaf(fmaf(c.w, gm.w, u.w), iv, bt.w);
            __stcs(op + (size_t)jj * 16, o);
        }

        // commit prefetch to the other buffer
        if (t + 1 < JT) {
            ((float4*)(cs[nxt] + rw * PADR))[f4] = pc;
            if (tid < 16) vC[nxt][tid] = pv;
        }
        __syncthreads();
    }
}

// ---------------- launch -------------------------------------------------------
#define KB_SMEM ((2080 + 8448 + 8448 + 4160 + 2048 + 2048) * 4)

extern "C" void kernel_launch(void* const* d_in, const int* in_sizes, int n_in,
                              void* d_out, int out_size) {
    const float* x     = (const float*)d_in[0];  // [2,768,512]
    const float* Wr    = (const float*)d_in[1];  // [64,512]
    const float* Wc    = (const float*)d_in[2];  // [64,512]
    const float* We    = (const float*)d_in[3];  // [64,64]
    const float* gamma = (const float*)d_in[4];  // [64]
    const float* beta  = (const float*)d_in[5];  // [64]
    float* out = (float*)d_out;                  // [2,768,768,64] fp32

    static int smem_set = 0;
    if (!smem_set) {
        cudaFuncSetAttribute(kB, cudaFuncAttributeMaxDynamicSharedMemorySize, KB_SMEM);
        smem_set = 1;
    }

    kB<<<96, 256, KB_SMEM>>>(x, Wr, Wc, We);
    kC<<<dim3(N_ / 16, B_, N_ / 16 / JT), 256>>>(gamma, beta, out);
}

// round 11
// speedup vs baseline: 1.2269x; 1.2269x over previous
#include <cuda_runtime.h>
#include <cstddef>
#include <cstdint>

#define B_   2
#define N_   768
#define BN_  1536
#define D_   512
#define E_   64
#define LN_EPS 1e-5f
#define PADR 68            // kC smem row pitch (floats)
#define XP   130           // kB x-tile pitch (floats)
#define WP   66            // kB weight-tile pitch (floats)
#define JT   8             // kC j-tiles per block

typedef unsigned long long ull;

// ---------------- scratch ----------------
__device__ float g_Rc[BN_ * E_];    // centered R'
__device__ float g_Cc[BN_ * E_];    // centered C'
__device__ float g_varR[BN_];
__device__ float g_varC[BN_];

// -------- f32x2 helpers --------
__device__ __forceinline__ void ffma2(ull& d, ull a, ull b) {
    asm("fma.rn.f32x2 %0, %1, %2, %0;" : "+l"(d) : "l"(a), "l"(b));
}
__device__ __forceinline__ ull pack2(float x) {
    ull r; unsigned u = __float_as_uint(x);
    asm("mov.b64 %0, {%1, %1};" : "=l"(r) : "r"(u));
    return r;
}

// ---------------- kernel B: the entire prologue, fused (unchanged R9) --------
extern __shared__ float sm_b[];
__global__ void __launch_bounds__(256) kB(const float* __restrict__ x,
                                          const float* __restrict__ Wr,
                                          const float* __restrict__ Wc,
                                          const float* __restrict__ We) {
    float* xs  = sm_b;                 // 2080
    float* wrs = sm_b + 2080;          // 8448
    float* wcs = wrs + 8448;           // 8448
    float* wes = wcs + 8448;           // 4160 (pitch 65)
    float* Trw = wes + 4160;           // 2048
    float* Tcw = Trw + 2048;           // 2048
    float* P   = sm_b + 2080;          // alias 16384 <= 16896

    int tid  = threadIdx.x;
    int f2   = tid & 31;
    int w    = tid >> 5;
    int row0 = blockIdx.x * 16;

    for (int idx = tid; idx < 4096; idx += 256) {
        int f = idx >> 6, e = idx & 63;
        wes[e * 65 + f] = We[f * E_ + e];
    }

    ull aR[16], aC[16];
#pragma unroll
    for (int r = 0; r < 16; r++) { aR[r] = 0ULL; aC[r] = 0ULL; }

    for (int c = 0; c < 4; c++) {
        int d0 = c * 128;
        for (int idx = tid; idx < 4096; idx += 256) {
            int fp = idx >> 7;
            int dd = idx & 127;
            float2 vr, vc;
            vr.x = Wr[(size_t)(2 * fp) * D_ + d0 + dd];
            vr.y = Wr[(size_t)(2 * fp + 1) * D_ + d0 + dd];
            vc.x = Wc[(size_t)(2 * fp) * D_ + d0 + dd];
            vc.y = Wc[(size_t)(2 * fp + 1) * D_ + d0 + dd];
            *(float2*)(wrs + dd * WP + 2 * fp) = vr;
            *(float2*)(wcs + dd * WP + 2 * fp) = vc;
        }
        for (int idx = tid; idx < 1024; idx += 256) {
            int r = idx >> 6, dd2 = idx & 63;
            *(float2*)(xs + r * XP + dd2 * 2) =
                *(const float2*)(x + (size_t)(row0 + r) * D_ + d0 + dd2 * 2);
        }
        __syncthreads();

        int wbase = w * 16;
#pragma unroll
        for (int p = 0; p < 8; p++) {
            int dd = wbase + p * 2;
            ull wr0 = *(const ull*)(wrs + dd * WP + 2 * f2);
            ull wr1 = *(const ull*)(wrs + (dd + 1) * WP + 2 * f2);
            ull wc0 = *(const ull*)(wcs + dd * WP + 2 * f2);
            ull wc1 = *(const ull*)(wcs + (dd + 1) * WP + 2 * f2);
#pragma unroll
            for (int r = 0; r < 16; r++) {
                float2 xv = *(const float2*)(xs + r * XP + dd);
                ull x0 = pack2(xv.x);
                ull x1 = pack2(xv.y);
                ffma2(aR[r], x0, wr0);
                ffma2(aR[r], x1, wr1);
                ffma2(aC[r], x0, wc0);
                ffma2(aC[r], x1, wc1);
            }
        }
        __syncthreads();
    }

#pragma unroll
    for (int r = 0; r < 16; r++) {
        *(ull*)(P + ((w * 2 + 0) * 16 + r) * E_ + 2 * f2) = aR[r];
        *(ull*)(P + ((w * 2 + 1) * 16 + r) * E_ + 2 * f2) = aC[r];
    }
    __syncthreads();

    {
        int row = tid >> 4;
        int fq  = tid & 15;
        float4 R4 = make_float4(0.f, 0.f, 0.f, 0.f);
        float4 C4 = make_float4(0.f, 0.f, 0.f, 0.f);
#pragma unroll
        for (int ww = 0; ww < 8; ww++) {
            float4 pr = *(const float4*)(P + ((ww * 2 + 0) * 16 + row) * E_ + fq * 4);
            float4 pc = *(const float4*)(P + ((ww * 2 + 1) * 16 + row) * E_ + fq * 4);
            R4.x += pr.x; R4.y += pr.y; R4.z += pr.z; R4.w += pr.w;
            C4.x += pc.x; C4.y += pc.y; C4.z += pc.z; C4.w += pc.w;
        }
        *(float4*)(Trw + row * E_ + fq * 4) = R4;
        *(float4*)(Tcw + row * E_ + fq * 4) = C4;
    }
    __syncthreads();

    int l  = tid & 31;
    int r0 = 2 * w, r1 = 2 * w + 1;
    float aR0l = 0.f, aR0h = 0.f, aR1l = 0.f, aR1h = 0.f;
    float aC0l = 0.f, aC0h = 0.f, aC1l = 0.f, aC1h = 0.f;
#pragma unroll 4
    for (int e = 0; e < E_; e++) {
        float wl = wes[e * 65 + l];
        float wh = wes[e * 65 + l + 32];
        float t0 = Trw[r0 * E_ + e];
        float t1 = Trw[r1 * E_ + e];
        float c0 = Tcw[r0 * E_ + e];
        float c1 = Tcw[r1 * E_ + e];
        aR0l = fmaf(t0, wl, aR0l); aR0h = fmaf(t0, wh, aR0h);
        aR1l = fmaf(t1, wl, aR1l); aR1h = fmaf(t1, wh, aR1h);
        aC0l = fmaf(c0, wl, aC0l); aC0h = fmaf(c0, wh, aC0h);
        aC1l = fmaf(c1, wl, aC1l); aC1h = fmaf(c1, wh, aC1h);
    }

    float sR0 = aR0l + aR0h, qR0 = aR0l * aR0l + aR0h * aR0h;
    float sR1 = aR1l + aR1h, qR1 = aR1l * aR1l + aR1h * aR1h;
    float sC0 = aC0l + aC0h, qC0 = aC0l * aC0l + aC0h * aC0h;
    float sC1 = aC1l + aC1h, qC1 = aC1l * aC1l + aC1h * aC1h;
#pragma unroll
    for (int o = 16; o; o >>= 1) {
        sR0 += __shfl_xor_sync(0xffffffffu, sR0, o);
        qR0 += __shfl_xor_sync(0xffffffffu, qR0, o);
        sR1 += __shfl_xor_sync(0xffffffffu, sR1, o);
        qR1 += __shfl_xor_sync(0xffffffffu, qR1, o);
        sC0 += __shfl_xor_sync(0xffffffffu, sC0, o);
        qC0 += __shfl_xor_sync(0xffffffffu, qC0, o);
        sC1 += __shfl_xor_sync(0xffffffffu, sC1, o);
        qC1 += __shfl_xor_sync(0xffffffffu, qC1, o);
    }
    float mR0 = sR0 * (1.f / 64.f), mR1 = sR1 * (1.f / 64.f);
    float mC0 = sC0 * (1.f / 64.f), mC1 = sC1 * (1.f / 64.f);
    int g0 = row0 + r0, g1 = row0 + r1;
    g_Rc[g0 * E_ + l]      = aR0l - mR0;
    g_Rc[g0 * E_ + l + 32] = aR0h - mR0;
    g_Rc[g1 * E_ + l]      = aR1l - mR1;
    g_Rc[g1 * E_ + l + 32] = aR1h - mR1;
    g_Cc[g0 * E_ + l]      = aC0l - mC0;
    g_Cc[g0 * E_ + l + 32] = aC0h - mC0;
    g_Cc[g1 * E_ + l]      = aC1l - mC1;
    g_Cc[g1 * E_ + l + 32] = aC1h - mC1;
    if (l == 0) {
        g_varR[g0] = qR0 * (1.f / 64.f) - mR0 * mR0;
        g_varR[g1] = qR1 * (1.f / 64.f) - mR1 * mR1;
        g_varC[g0] = qC0 * (1.f / 64.f) - mC0 * mC0;
        g_varC[g1] = qC1 * (1.f / 64.f) - mC1 * mC1;
    }
}

// ---------------- kernel C: R8 pipelined epilogue, 5 blocks/SM ---------------
// grid (48, 2, 6) = 576 blocks. Double-buffered cs, register prefetch,
// gamma folded; iv read as scalar smem broadcast (low reg pressure).
__global__ void __launch_bounds__(256, 5) kC(const float* __restrict__ gamma,
                                             const float* __restrict__ beta,
                                             float* __restrict__ out) {
    __shared__ float rs[16 * PADR];
    __shared__ float cs[2][16 * PADR];
    __shared__ float vR[16];
    __shared__ float vC[2][16];
    __shared__ float inv[256];

    int i0 = blockIdx.x * 16;
    int b  = blockIdx.y;
    int jg = blockIdx.z;
    int tid = threadIdx.x;
    int rowR = b * N_ + i0;
    int rw = tid >> 4;
    int f4 = tid & 15;

    ((float4*)(rs + rw * PADR))[f4] = ((const float4*)(g_Rc + (size_t)(rowR + rw) * E_))[f4];
    if (tid < 16) vR[tid] = g_varR[rowR + tid];
    {
        int rowC = b * N_ + jg * JT * 16;
        ((float4*)(cs[0] + rw * PADR))[f4] = ((const float4*)(g_Cc + (size_t)(rowC + rw) * E_))[f4];
        if (tid < 16) vC[0][tid] = g_varC[rowC + tid];
    }
    __syncthreads();

    float4 gm = __ldg((const float4*)gamma + f4);
    float4 bt = __ldg((const float4*)beta + f4);
    float4 rr = ((const float4*)(rs + rw * PADR))[f4];
    float4 u;                            // u = r' * gamma
    u.x = rr.x * gm.x; u.y = rr.y * gm.y; u.z = rr.z * gm.z; u.w = rr.w * gm.w;

    for (int t = 0; t < JT; t++) {
        int cur = t & 1, nxt = cur ^ 1;
        float* csc = cs[cur];

        // register prefetch of next tile (hidden behind dots + stores)
        float4 pc;
        float pv = 0.f;
        if (t + 1 < JT) {
            int rowCn = b * N_ + (jg * JT + t + 1) * 16;
            pc = ((const float4*)(g_Cc + (size_t)(rowCn + rw) * E_))[f4];
            if (tid < 16) pv = g_varC[rowCn + tid];
        }

        // phase A: one 64-wide dot per thread -> inv std
        {
            int ii = tid >> 4, jj = tid & 15;
            const float4* r4 = (const float4*)(rs + ii * PADR);
            const float4* c4 = (const float4*)(csc + jj * PADR);
            float d = 0.f;
#pragma unroll
            for (int k = 0; k < 16; k++) {
                float4 a = r4[k], c = c4[k];
                d = fmaf(a.x, c.x, d);
                d = fmaf(a.y, c.y, d);
                d = fmaf(a.z, c.z, d);
                d = fmaf(a.w, c.w, d);
            }
            float var = vR[ii] + vC[cur][jj] + d * (2.f / 64.f);
            inv[tid] = rsqrtf(var + LN_EPS);
        }
        __syncthreads();

        // phase B: streaming stores; iv via scalar smem broadcast
        const float* invg = inv + rw * 16;
        float4* op = (float4*)out +
                     ((size_t)(b * N_ + i0 + rw) * N_ + (jg * JT + t) * 16) * 16 + f4;
#pragma unroll
        for (int jj = 0; jj < 16; jj++) {
            float4 c = ((const float4*)(csc + jj * PADR))[f4];
            float iv = invg[jj];
            float4 o;
            o.x = fmaf(fmaf(c.x, gm.x, u.x), iv, bt.x);
            o.y = fmaf(fmaf(c.y, gm.y, u.y), iv, bt.y);
            o.z = fmaf(fmaf(c.z, gm.z, u.z), iv, bt.z);
            o.w = fmaf(fmaf(c.w, gm.w, u.w), iv, bt.w);
            __stcs(op + (size_t)jj * 16, o);
        }

        // commit prefetch to the other buffer
        if (t + 1 < JT) {
            ((float4*)(cs[nxt] + rw * PADR))[f4] = pc;
            if (tid < 16) vC[nxt][tid] = pv;
        }
        __syncthreads();
    }
}

// ---------------- launch -------------------------------------------------------
#define KB_SMEM ((2080 + 8448 + 8448 + 4160 + 2048 + 2048) * 4)

extern "C" void kernel_launch(void* const* d_in, const int* in_sizes, int n_in,
                              void* d_out, int out_size) {
    const float* x     = (const float*)d_in[0];  // [2,768,512]
    const float* Wr    = (const float*)d_in[1];  // [64,512]
    const float* Wc    = (const float*)d_in[2];  // [64,512]
    const float* We    = (const float*)d_in[3];  // [64,64]
    const float* gamma = (const float*)d_in[4];  // [64]
    const float* beta  = (const float*)d_in[5];  // [64]
    float* out = (float*)d_out;                  // [2,768,768,64] fp32

    static int smem_set = 0;
    if (!smem_set) {
        cudaFuncSetAttribute(kB, cudaFuncAttributeMaxDynamicSharedMemorySize, KB_SMEM);
        smem_set = 1;
    }

    kB<<<96, 256, KB_SMEM>>>(x, Wr, Wc, We);
    kC<<<dim3(N_ / 16, B_, N_ / 16 / JT), 256>>>(gamma, beta, out);
}

// round 12
// speedup vs baseline: 1.2641x; 1.0304x over previous
#include <cuda_runtime.h>
#include <cstddef>
#include <cstdint>

#define B_   2
#define N_   768
#define BN_  1536
#define D_   512
#define E_   64
#define LN_EPS 1e-5f
#define PADR 68            // kC smem row pitch (floats)
#define XP   130           // kB x-tile pitch (floats)
#define WP   66            // kB weight-tile pitch (floats)
#define JT   8             // kC j-tiles per block

typedef unsigned long long ull;

// ---------------- scratch ----------------
__device__ float g_Rc[BN_ * E_];    // centered R'
__device__ float g_Cc[BN_ * E_];    // centered C'
__device__ float g_varR[BN_];
__device__ float g_varC[BN_];

// -------- f32x2 helpers --------
__device__ __forceinline__ void ffma2(ull& d, ull a, ull b) {
    asm("fma.rn.f32x2 %0, %1, %2, %0;" : "+l"(d) : "l"(a), "l"(b));
}
__device__ __forceinline__ ull pack2(float x) {
    ull r; unsigned u = __float_as_uint(x);
    asm("mov.b64 %0, {%1, %1};" : "=l"(r) : "r"(u));
    return r;
}

// ---------------- kernel B: fused prologue, 8 rows/block, 2 blocks/SM --------
// grid 192, block 256.
// smem floats: xs 1040 | wrs 8448 | wcs 8448 | wes 4160 | Trw 1024 | Tcw 1024
// P (8 warps x 2 x 8 rows x 64 = 8192) aliases wrs.
extern __shared__ float sm_b[];
__global__ void __launch_bounds__(256) kB(const float* __restrict__ x,
                                          const float* __restrict__ Wr,
                                          const float* __restrict__ Wc,
                                          const float* __restrict__ We) {
    float* xs  = sm_b;                 // 1040
    float* wrs = sm_b + 1040;          // 8448
    float* wcs = wrs + 8448;           // 8448
    float* wes = wcs + 8448;           // 4160 (pitch 65)
    float* Trw = wes + 4160;           // 1024
    float* Tcw = Trw + 1024;           // 1024
    float* P   = sm_b + 1040;          // alias 8192 <= 16896

    int tid  = threadIdx.x;
    int f2   = tid & 31;
    int w    = tid >> 5;
    int row0 = blockIdx.x * 8;

    // We transposed: wes[e*65+f] = We[f][e]
    for (int idx = tid; idx < 4096; idx += 256) {
        int f = idx >> 6, e = idx & 63;
        wes[e * 65 + f] = We[f * E_ + e];
    }

    ull aR[8], aC[8];
#pragma unroll
    for (int r = 0; r < 8; r++) { aR[r] = 0ULL; aC[r] = 0ULL; }

    for (int c = 0; c < 4; c++) {
        int d0 = c * 128;
        // transpose weight chunk: LDG coalesced along dd, STS.64 stride 66
        for (int idx = tid; idx < 4096; idx += 256) {
            int fp = idx >> 7;          // 0..31
            int dd = idx & 127;
            float2 vr, vc;
            vr.x = Wr[(size_t)(2 * fp) * D_ + d0 + dd];
            vr.y = Wr[(size_t)(2 * fp + 1) * D_ + d0 + dd];
            vc.x = Wc[(size_t)(2 * fp) * D_ + d0 + dd];
            vc.y = Wc[(size_t)(2 * fp + 1) * D_ + d0 + dd];
            *(float2*)(wrs + dd * WP + 2 * fp) = vr;
            *(float2*)(wcs + dd * WP + 2 * fp) = vc;
        }
        // x tile: 8 rows x 128 dd
        for (int idx = tid; idx < 512; idx += 256) {
            int r = idx >> 6, dd2 = idx & 63;
            *(float2*)(xs + r * XP + dd2 * 2) =
                *(const float2*)(x + (size_t)(row0 + r) * D_ + d0 + dd2 * 2);
        }
        __syncthreads();

        int wbase = w * 16;
#pragma unroll
        for (int p = 0; p < 8; p++) {
            int dd = wbase + p * 2;
            ull wr0 = *(const ull*)(wrs + dd * WP + 2 * f2);
            ull wr1 = *(const ull*)(wrs + (dd + 1) * WP + 2 * f2);
            ull wc0 = *(const ull*)(wcs + dd * WP + 2 * f2);
            ull wc1 = *(const ull*)(wcs + (dd + 1) * WP + 2 * f2);
#pragma unroll
            for (int r = 0; r < 8; r++) {
                float2 xv = *(const float2*)(xs + r * XP + dd);
                ull x0 = pack2(xv.x);
                ull x1 = pack2(xv.y);
                ffma2(aR[r], x0, wr0);
                ffma2(aR[r], x1, wr1);
                ffma2(aC[r], x0, wc0);
                ffma2(aC[r], x1, wc1);
            }
        }
        __syncthreads();
    }

    // per-warp partials into P (aliases weight buffers)
#pragma unroll
    for (int r = 0; r < 8; r++) {
        *(ull*)(P + ((w * 2 + 0) * 8 + r) * E_ + 2 * f2) = aR[r];
        *(ull*)(P + ((w * 2 + 1) * 8 + r) * E_ + 2 * f2) = aC[r];
    }
    __syncthreads();

    // reduce 8 warp-partials -> raw T rows in smem
    {
        int row = tid >> 5;             // 0..7
        int arr = (tid >> 4) & 1;
        int fq  = tid & 15;
        float4 A = make_float4(0.f, 0.f, 0.f, 0.f);
#pragma unroll
        for (int ww = 0; ww < 8; ww++) {
            float4 p = *(const float4*)(P + ((ww * 2 + arr) * 8 + row) * E_ + fq * 4);
            A.x += p.x; A.y += p.y; A.z += p.z; A.w += p.w;
        }
        float* dst = arr ? Tcw : Trw;
        *(float4*)(dst + row * E_ + fq * 4) = A;
    }
    __syncthreads();

    // edge apply: warp w -> row w; lane l -> f = l and l+32
    int l = tid & 31;
    float aRl = 0.f, aRh = 0.f, aCl = 0.f, aCh = 0.f;
#pragma unroll 8
    for (int e = 0; e < E_; e++) {
        float wl = wes[e * 65 + l];
        float wh = wes[e * 65 + l + 32];
        float t0 = Trw[w * E_ + e];      // broadcast
        float c0 = Tcw[w * E_ + e];      // broadcast
        aRl = fmaf(t0, wl, aRl); aRh = fmaf(t0, wh, aRh);
        aCl = fmaf(c0, wl, aCl); aCh = fmaf(c0, wh, aCh);
    }

    // stats over the 64 f of the row (single warp)
    float sR = aRl + aRh, qR = aRl * aRl + aRh * aRh;
    float sC = aCl + aCh, qC = aCl * aCl + aCh * aCh;
#pragma unroll
    for (int o = 16; o; o >>= 1) {
        sR += __shfl_xor_sync(0xffffffffu, sR, o);
        qR += __shfl_xor_sync(0xffffffffu, qR, o);
        sC += __shfl_xor_sync(0xffffffffu, sC, o);
        qC += __shfl_xor_sync(0xffffffffu, qC, o);
    }
    float mR = sR * (1.f / 64.f);
    float mC = sC * (1.f / 64.f);
    int grow = row0 + w;
    g_Rc[grow * E_ + l]      = aRl - mR;
    g_Rc[grow * E_ + l + 32] = aRh - mR;
    g_Cc[grow * E_ + l]      = aCl - mC;
    g_Cc[grow * E_ + l + 32] = aCh - mC;
    if (l == 0) {
        g_varR[grow] = qR * (1.f / 64.f) - mR * mR;
        g_varC[grow] = qC * (1.f / 64.f) - mC * mC;
    }
}

// ---------------- kernel C: R8 pipelined epilogue (EXACT, measured 52.4us) ---
__global__ void __launch_bounds__(256, 4) kC(const float* __restrict__ gamma,
                                             const float* __restrict__ beta,
                                             float* __restrict__ out) {
    __shared__ float rs[16 * PADR];
    __shared__ float cs[2][16 * PADR];
    __shared__ float vR[16];
    __shared__ float vC[2][16];
    __shared__ float inv[256];

    int i0 = blockIdx.x * 16;
    int b  = blockIdx.y;
    int jg = blockIdx.z;
    int tid = threadIdx.x;
    int rowR = b * N_ + i0;
    int rw = tid >> 4;
    int f4 = tid & 15;

    ((float4*)(rs + rw * PADR))[f4] = ((const float4*)(g_Rc + (size_t)(rowR + rw) * E_))[f4];
    if (tid < 16) vR[tid] = g_varR[rowR + tid];
    {
        int rowC = b * N_ + jg * JT * 16;
        ((float4*)(cs[0] + rw * PADR))[f4] = ((const float4*)(g_Cc + (size_t)(rowC + rw) * E_))[f4];
        if (tid < 16) vC[0][tid] = g_varC[rowC + tid];
    }
    __syncthreads();

    float4 gm = __ldg((const float4*)gamma + f4);
    float4 bt = __ldg((const float4*)beta + f4);
    float4 rr = ((const float4*)(rs + rw * PADR))[f4];
    float4 u;
    u.x = rr.x * gm.x; u.y = rr.y * gm.y; u.z = rr.z * gm.z; u.w = rr.w * gm.w;

    for (int t = 0; t < JT; t++) {
        int cur = t & 1, nxt = cur ^ 1;
        float* csc = cs[cur];

        float4 pc;
        float pv = 0.f;
        if (t + 1 < JT) {
            int rowCn = b * N_ + (jg * JT + t + 1) * 16;
            pc = ((const float4*)(g_Cc + (size_t)(rowCn + rw) * E_))[f4];
            if (tid < 16) pv = g_varC[rowCn + tid];
        }

        {
            int ii = tid >> 4, jj = tid & 15;
            const float4* r4 = (const float4*)(rs + ii * PADR);
            const float4* c4 = (const float4*)(csc + jj * PADR);
            float d = 0.f;
#pragma unroll
            for (int k = 0; k < 16; k++) {
                float4 a = r4[k], c = c4[k];
                d = fmaf(a.x, c.x, d);
                d = fmaf(a.y, c.y, d);
                d = fmaf(a.z, c.z, d);
                d = fmaf(a.w, c.w, d);
            }
            float var = vR[ii] + vC[cur][jj] + d * (2.f / 64.f);
            inv[tid] = rsqrtf(var + LN_EPS);
        }
        __syncthreads();

        const float* invg = inv + rw * 16;
        const float4* ivp = (const float4*)invg;
        float4 iva = ivp[0], ivb = ivp[1], ivc = ivp[2], ivd = ivp[3];
        float ivs[16] = {iva.x, iva.y, iva.z, iva.w, ivb.x, ivb.y, ivb.z, ivb.w,
                         ivc.x, ivc.y, ivc.z, ivc.w, ivd.x, ivd.y, ivd.z, ivd.w};
        float4* op = (float4*)out +
                     ((size_t)(b * N_ + i0 + rw) * N_ + (jg * JT + t) * 16) * 16 + f4;
#pragma unroll
        for (int jj = 0; jj < 16; jj++) {
            float4 c = ((const float4*)(csc + jj * PADR))[f4];
            float iv = ivs[jj];
            float4 o;
            o.x = fmaf(fmaf(c.x, gm.x, u.x), iv, bt.x);
            o.y = fmaf(fmaf(c.y, gm.y, u.y), iv, bt.y);
            o.z = fmaf(fmaf(c.z, gm.z, u.z), iv, bt.z);
            o.w = fmaf(fmaf(c.w, gm.w, u.w), iv, bt.w);
            __stcs(op + (size_t)jj * 16, o);
        }

        if (t + 1 < JT) {
            ((float4*)(cs[nxt] + rw * PADR))[f4] = pc;
            if (tid < 16) vC[nxt][tid] = pv;
        }
        __syncthreads();
    }
}

// ---------------- launch -------------------------------------------------------
#define KB_SMEM ((1040 + 8448 + 8448 + 4160 + 1024 + 1024) * 4)

extern "C" void kernel_launch(void* const* d_in, const int* in_sizes, int n_in,
                              void* d_out, int out_size) {
    const float* x     = (const float*)d_in[0];  // [2,768,512]
    const float* Wr    = (const float*)d_in[1];  // [64,512]
    const float* Wc    = (const float*)d_in[2];  // [64,512]
    const float* We    = (const float*)d_in[3];  // [64,64]
    const float* gamma = (const float*)d_in[4];  // [64]
    const float* beta  = (const float*)d_in[5];  // [64]
    float* out = (float*)d_out;                  // [2,768,768,64] fp32

    static int smem_set = 0;
    if (!smem_set) {
        cudaFuncSetAttribute(kB, cudaFuncAttributeMaxDynamicSharedMemorySize, KB_SMEM);
        smem_set = 1;
    }

    kB<<<192, 256, KB_SMEM>>>(x, Wr, Wc, We);
    kC<<<dim3(N_ / 16, B_, N_ / 16 / JT), 256>>>(gamma, beta, out);
}